// round 4
// baseline (speedup 1.0000x reference)
#include <cuda_runtime.h>
#include <math.h>

#define DEV_INLINE __device__ __forceinline__

namespace {
constexpr int Bb  = 256, T = 64, BT = Bb * T;
constexpr int L = 1024, S = 512, NC = 239;
constexpr int DX = 2048, DXS = 1280, CAT = DX + S;   // 2560
constexpr int GL = 4 * L, GS = 4 * S;                 // 4096, 2048
constexpr int RS_OFF = Bb * NC;                       // 61184
constexpr float BN_RS = 0.99999500003749969f;         // 1/sqrt(1+1e-5)
constexpr int BK = 32;
}

__device__ float g_featcat[(size_t)BT * CAT];
__device__ float g_igl[(size_t)BT * GL];
__device__ float g_igs[(size_t)BT * GS];
__device__ float g_gpre[BT * 2];
__device__ float g_Wihl[(size_t)GL * CAT];
__device__ float g_Whhl[(size_t)GL * L];
__device__ float g_Wihs[(size_t)GS * S];
__device__ float g_Whhs[(size_t)GS * S];
__device__ float g_bl[GL];
__device__ float g_bs[GS];
__device__ float g_hl[2][Bb * L];
__device__ float g_cl[2][Bb * L];
__device__ float g_hs[2][Bb * S];
__device__ float g_cs[2][Bb * S];
__device__ int   g_rflag[Bb];

// C[m,n] = sum_k A[m,k]*B[n,k]  (both row-major, NT)
template <int BM, int BN, int TM, int TN>
DEV_INLINE void gemm_core(const float* __restrict__ A, int lda,
                          const float* __restrict__ Bw, int ldb,
                          int M, int N, int K, int m0, int n0,
                          float* __restrict__ As, float* __restrict__ Bs,
                          float (&acc)[TM][TN])
{
    constexpr int THREADS = (BM / TM) * (BN / TN);
    constexpr int LDAS = BM + 4, LDBS = BN + 4;
    const int tid = threadIdx.x;
    const int tx = tid % (BN / TN), ty = tid / (BN / TN);
    const int tm0 = ty * TM, tn0 = tx * TN;

    #pragma unroll
    for (int i = 0; i < TM; i++)
        #pragma unroll
        for (int j = 0; j < TN; j++) acc[i][j] = 0.f;

    for (int k0 = 0; k0 < K; k0 += BK) {
        __syncthreads();
        #pragma unroll
        for (int i = 0; i < (BM * BK / 4) / THREADS; i++) {
            int idx = tid + i * THREADS;
            int row = idx / (BK / 4), kq = idx % (BK / 4);
            float4 v = make_float4(0.f, 0.f, 0.f, 0.f);
            int gm = m0 + row;
            if (gm < M) v = *reinterpret_cast<const float4*>(A + (size_t)gm * lda + k0 + kq * 4);
            As[(kq * 4 + 0) * LDAS + row] = v.x;
            As[(kq * 4 + 1) * LDAS + row] = v.y;
            As[(kq * 4 + 2) * LDAS + row] = v.z;
            As[(kq * 4 + 3) * LDAS + row] = v.w;
        }
        #pragma unroll
        for (int i = 0; i < (BN * BK / 4) / THREADS; i++) {
            int idx = tid + i * THREADS;
            int row = idx / (BK / 4), kq = idx % (BK / 4);
            float4 v = make_float4(0.f, 0.f, 0.f, 0.f);
            int gn = n0 + row;
            if (gn < N) v = *reinterpret_cast<const float4*>(Bw + (size_t)gn * ldb + k0 + kq * 4);
            Bs[(kq * 4 + 0) * LDBS + row] = v.x;
            Bs[(kq * 4 + 1) * LDBS + row] = v.y;
            Bs[(kq * 4 + 2) * LDBS + row] = v.z;
            Bs[(kq * 4 + 3) * LDBS + row] = v.w;
        }
        __syncthreads();
        #pragma unroll
        for (int kk = 0; kk < BK; kk++) {
            float ra[TM], rb[TN];
            #pragma unroll
            for (int i = 0; i < TM; i++) ra[i] = As[kk * LDAS + tm0 + i];
            #pragma unroll
            for (int j = 0; j < TN; j++) rb[j] = Bs[kk * LDBS + tn0 + j];
            #pragma unroll
            for (int i = 0; i < TM; i++)
                #pragma unroll
                for (int j = 0; j < TN; j++)
                    acc[i][j] = fmaf(ra[i], rb[j], acc[i][j]);
        }
    }
}

// MODE 0: +bias   MODE 1: relu((v+bias)*gamma*BN_RS + beta)
template <int MODE>
__global__ void __launch_bounds__(256)
gemm_nt(const float* __restrict__ A, int lda, const float* __restrict__ Bw, int ldb,
        float* __restrict__ C, int ldc, int M, int N, int K,
        const float* __restrict__ bias, const float* __restrict__ gamma,
        const float* __restrict__ beta)
{
    constexpr int BM = 128, BN = 128, TM = 8, TN = 8;
    __shared__ float As[BK * (BM + 4)];
    __shared__ float Bs[BK * (BN + 4)];
    const int m0 = blockIdx.y * BM, n0 = blockIdx.x * BN;
    float acc[TM][TN];
    gemm_core<BM, BN, TM, TN>(A, lda, Bw, ldb, M, N, K, m0, n0, As, Bs, acc);
    const int tid = threadIdx.x;
    const int tx = tid % (BN / TN), ty = tid / (BN / TN);
    #pragma unroll
    for (int i = 0; i < TM; i++) {
        int m = m0 + ty * TM + i;
        if (m >= M) continue;
        #pragma unroll
        for (int j = 0; j < TN; j++) {
            int n = n0 + tx * TN + j;
            if (n >= N) continue;
            float v = acc[i][j] + bias[n];
            if (MODE == 1) v = fmaxf(fmaf(v, gamma[n] * BN_RS, beta[n]), 0.f);
            C[(size_t)m * ldc + n] = v;
        }
    }
}

DEV_INLINE float sigf(float x) { return 1.0f / (1.0f + expf(-x)); }

// per step: small LSTM cell (fused in GEMM epilogue) + hard-gate decision
__global__ void __launch_bounds__(256)
step_small(int t, int cur, const float* __restrict__ Wg, float* __restrict__ dout)
{
    constexpr int BM = 64, BN = 128, TM = 4, TN = 8;
    constexpr int GX = GS / BN, GY = Bb / BM;   // 16, 4
    const int nxt = cur ^ 1;
    const int bid = blockIdx.x;
    __shared__ float As[BK * (BM + 4)];
    __shared__ float Bs[BK * (BN + 4)];

    if (bid < GX * GY) {
        const int m0 = (bid / GX) * BM, n0 = (bid % GX) * BN;
        float acc[TM][TN];
        gemm_core<BM, BN, TM, TN>(g_hs[cur], S, g_Whhs, S, Bb, GS, S, m0, n0, As, Bs, acc);
        const int tid = threadIdx.x;
        const int tx = tid % (BN / TN), ty = tid / (BN / TN);
        #pragma unroll
        for (int i = 0; i < TM; i++) {
            int b = m0 + ty * TM + i;
            size_t row = (size_t)b * T + t;
            #pragma unroll
            for (int q = 0; q < TN / 4; q++) {
                int n = n0 + tx * TN + q * 4;
                int j = n >> 2;
                float4 ig = *reinterpret_cast<const float4*>(g_igs + row * GS + n);
                float c2 = sigf(acc[i][q*4+1] + ig.y) * g_cs[cur][b * S + j]
                         + sigf(acc[i][q*4+0] + ig.x) * tanhf(acc[i][q*4+2] + ig.z);
                float h2 = sigf(acc[i][q*4+3] + ig.w) * tanhf(c2);
                g_cs[nxt][b * S + j] = c2;
                g_hs[nxt][b * S + j] = h2;
            }
        }
    } else {
        const int gb = bid - GX * GY;
        const int tid = threadIdx.x;
        const int sub = tid >> 4, lane = tid & 15;
        const int b = gb * 16 + sub;
        const float* hl = g_hl[cur] + b * L;
        const float* cl = g_cl[cur] + b * L;
        const float* w0 = Wg + S;
        const float* w1 = Wg + CAT + S;
        float l0 = 0.f, l1 = 0.f;
        for (int k = lane; k < L; k += 16) {
            float hv = hl[k], cv = cl[k];
            l0 = fmaf(hv, w0[k], l0); l0 = fmaf(cv, w0[L + k], l0);
            l1 = fmaf(hv, w1[k], l1); l1 = fmaf(cv, w1[L + k], l1);
        }
        #pragma unroll
        for (int off = 8; off; off >>= 1) {
            l0 += __shfl_down_sync(0xffffffffu, l0, off, 16);
            l1 += __shfl_down_sync(0xffffffffu, l1, off, 16);
        }
        if (lane == 0) {
            int row = b * T + t;
            l0 += g_gpre[row * 2 + 0];
            l1 += g_gpre[row * 2 + 1];
            int pick1 = (l1 > l0);
            g_rflag[b] = pick1 ? 0 : 1;
            size_t o = (size_t)RS_OFF + ((size_t)t * Bb + b) * 2;
            dout[o]     = pick1 ? 0.0f : 1.0f;
            dout[o + 1] = pick1 ? 1.0f : 0.0f;
        }
    }
}

// per step: large LSTM cell + gated combine (fused epilogue)
__global__ void __launch_bounds__(256)
step_large(int t, int cur)
{
    constexpr int BM = 64, BN = 128, TM = 4, TN = 8;
    const int nxt = cur ^ 1;
    __shared__ float As[BK * (BM + 4)];
    __shared__ float Bs[BK * (BN + 4)];
    const int m0 = blockIdx.y * BM, n0 = blockIdx.x * BN;
    float acc[TM][TN];
    gemm_core<BM, BN, TM, TN>(g_hl[cur], L, g_Whhl, L, Bb, GL, L, m0, n0, As, Bs, acc);
    const int tid = threadIdx.x;
    const int tx = tid % (BN / TN), ty = tid / (BN / TN);
    #pragma unroll
    for (int i = 0; i < TM; i++) {
        int b = m0 + ty * TM + i;
        size_t row = (size_t)b * T + t;
        int r0 = g_rflag[b];
        #pragma unroll
        for (int q = 0; q < TN / 4; q++) {
            int n = n0 + tx * TN + q * 4;
            int j = n >> 2;
            float4 ig = *reinterpret_cast<const float4*>(g_igl + row * GL + n);
            float cold = g_cl[cur][b * L + j];
            float hold = g_hl[cur][b * L + j];
            float c2 = sigf(acc[i][q*4+1] + ig.y) * cold
                     + sigf(acc[i][q*4+0] + ig.x) * tanhf(acc[i][q*4+2] + ig.z);
            float h2 = sigf(acc[i][q*4+3] + ig.w) * tanhf(c2);
            float hn, cn;
            if (r0)         { hn = h2;                   cn = c2; }
            else if (j < S) { hn = g_hs[nxt][b * S + j]; cn = g_cs[nxt][b * S + j]; }
            else            { hn = hold;                 cn = cold; }
            g_hl[nxt][b * L + j] = hn;
            g_cl[nxt][b * L + j] = cn;
        }
    }
}

__global__ void permute_w(const float* __restrict__ src, float* __restrict__ dst,
                          int H, int K)
{
    size_t total = (size_t)4 * H * K;
    size_t stride = (size_t)gridDim.x * blockDim.x;
    for (size_t i = (size_t)blockIdx.x * blockDim.x + threadIdx.x; i < total; i += stride) {
        size_t k = i % K;
        int n = (int)(i / K), j = n >> 2, g = n & 3;
        dst[i] = src[(size_t)(g * H + j) * K + k];
    }
}

__global__ void permute_bias(const float* __restrict__ b1, const float* __restrict__ b2,
                             float* __restrict__ dst, int H)
{
    int n = blockIdx.x * blockDim.x + threadIdx.x;
    if (n < 4 * H) { int j = n >> 2, g = n & 3; dst[n] = b1[g * H + j] + b2[g * H + j]; }
}

__global__ void init_states()
{
    int i = blockIdx.x * blockDim.x + threadIdx.x;
    int stride = gridDim.x * blockDim.x;
    for (int k = i; k < Bb * L; k += stride) { g_hl[0][k] = 0.f; g_cl[0][k] = 0.f; }
    for (int k = i; k < Bb * S; k += stride) { g_hs[0][k] = 0.f; g_cs[0][k] = 0.f; }
}

__global__ void gpre_kernel(const float* __restrict__ Wg, const float* __restrict__ bg)
{
    int row = blockIdx.x * 8 + (threadIdx.x >> 5);
    int lane = threadIdx.x & 31;
    if (row >= BT) return;
    const float* s = g_featcat + (size_t)row * CAT + DX;
    float l0 = 0.f, l1 = 0.f;
    for (int k = lane; k < S; k += 32) {
        float v = s[k];
        l0 = fmaf(v, Wg[k], l0);
        l1 = fmaf(v, Wg[CAT + k], l1);
    }
    #pragma unroll
    for (int off = 16; off; off >>= 1) {
        l0 += __shfl_down_sync(0xffffffffu, l0, off);
        l1 += __shfl_down_sync(0xffffffffu, l1, off);
    }
    if (lane == 0) {
        g_gpre[row * 2 + 0] = l0 + bg[0];
        g_gpre[row * 2 + 1] = l1 + bg[1];
    }
}

extern "C" void kernel_launch(void* const* d_in, const int* in_sizes, int n_in,
                              void* d_out, int out_size)
{
    const float* x     = (const float*)d_in[0];
    const float* xs    = (const float*)d_in[1];
    const float* W_p   = (const float*)d_in[2];
    const float* b_p   = (const float*)d_in[3];
    const float* g_p   = (const float*)d_in[4];
    const float* be_p  = (const float*)d_in[5];
    const float* W_s   = (const float*)d_in[6];
    const float* b_s   = (const float*)d_in[7];
    const float* g_s   = (const float*)d_in[8];
    const float* be_s  = (const float*)d_in[9];
    const float* Wih_l = (const float*)d_in[10];
    const float* Whh_l = (const float*)d_in[11];
    const float* bih_l = (const float*)d_in[12];
    const float* bhh_l = (const float*)d_in[13];
    const float* Wih_s = (const float*)d_in[14];
    const float* Whh_s = (const float*)d_in[15];
    const float* bih_s = (const float*)d_in[16];
    const float* bhh_s = (const float*)d_in[17];
    const float* W_g   = (const float*)d_in[18];
    const float* b_g   = (const float*)d_in[19];
    const float* W_c   = (const float*)d_in[20];
    const float* b_c   = (const float*)d_in[21];
    float* out = (float*)d_out;
    (void)in_sizes; (void)n_in; (void)out_size;

    float *featcat, *igl, *igs, *Wihl, *Whhl, *Wihs, *Whhs, *bl, *bs, *hl0;
    cudaGetSymbolAddress((void**)&featcat, g_featcat);
    cudaGetSymbolAddress((void**)&igl,  g_igl);
    cudaGetSymbolAddress((void**)&igs,  g_igs);
    cudaGetSymbolAddress((void**)&Wihl, g_Wihl);
    cudaGetSymbolAddress((void**)&Whhl, g_Whhl);
    cudaGetSymbolAddress((void**)&Wihs, g_Wihs);
    cudaGetSymbolAddress((void**)&Whhs, g_Whhs);
    cudaGetSymbolAddress((void**)&bl,   g_bl);
    cudaGetSymbolAddress((void**)&bs,   g_bs);
    cudaGetSymbolAddress((void**)&hl0,  g_hl);

    init_states<<<256, 256>>>();
    permute_w<<<2048, 256>>>(Wih_l, Wihl, L, CAT);
    permute_w<<<2048, 256>>>(Whh_l, Whhl, L, L);
    permute_w<<<1024, 256>>>(Wih_s, Wihs, S, S);
    permute_w<<<1024, 256>>>(Whh_s, Whhs, S, S);
    permute_bias<<<(GL + 255) / 256, 256>>>(bih_l, bhh_l, bl, L);
    permute_bias<<<(GS + 255) / 256, 256>>>(bih_s, bhh_s, bs, S);

    // feats = bn_relu(x @ W_p^T + b_p) -> featcat[:, :2048]
    gemm_nt<1><<<dim3(DX / 128, BT / 128), 256>>>(x, DX, W_p, DX, featcat, CAT,
                                                  BT, DX, DX, b_p, g_p, be_p);
    // sfeats = bn_relu(xs @ W_s^T + b_s) -> featcat[:, 2048:]
    gemm_nt<1><<<dim3(S / 128, BT / 128), 256>>>(xs, DXS, W_s, DXS, featcat + DX, CAT,
                                                 BT, S, DXS, b_s, g_s, be_s);
    // input-side gate preactivations (permuted), biases folded in
    gemm_nt<0><<<dim3(GS / 128, BT / 128), 256>>>(featcat + DX, CAT, Wihs, S, igs, GS,
                                                  BT, GS, S, bs, nullptr, nullptr);
    gemm_nt<0><<<dim3(GL / 128, BT / 128), 256>>>(featcat, CAT, Wihl, CAT, igl, GL,
                                                  BT, GL, CAT, bl, nullptr, nullptr);
    gpre_kernel<<<BT / 8, 256>>>(W_g, b_g);

    for (int t = 0; t < T; t++) {
        int cur = t & 1;
        step_small<<<(GS / 128) * (Bb / 64) + Bb / 16, 256>>>(t, cur, W_g, out);
        step_large<<<dim3(GL / 128, Bb / 64), 256>>>(t, cur);
    }
    // logits = h_l @ W_c^T + b_c   (final states land in buffer 0 after 64 steps)
    gemm_nt<0><<<dim3(2, 2), 256>>>(hl0, L, W_c, L, out, NC, Bb, NC, L,
                                    b_c, nullptr, nullptr);
}

// round 5
// speedup vs baseline: 1.0030x; 1.0030x over previous
#include <cuda_runtime.h>
#include <math.h>

#define DEV_INLINE __device__ __forceinline__

namespace {
constexpr int Bb  = 256, T = 64, BT = Bb * T;
constexpr int L = 1024, S = 512, NC = 239;
constexpr int DX = 2048, DXS = 1280, CAT = DX + S;   // 2560
constexpr int GL = 4 * L, GS = 4 * S;                 // 4096, 2048
constexpr int RS_OFF = Bb * NC;                       // 61184
constexpr float BN_RS = 0.99999500003749969f;         // 1/sqrt(1+1e-5)
constexpr int BK = 32;
}

__device__ float g_featcat[(size_t)BT * CAT];
__device__ float g_igl[(size_t)BT * GL];
__device__ float g_igs[(size_t)BT * GS];
__device__ float g_gpre[BT * 2];
__device__ float g_Wihl[(size_t)GL * CAT];
__device__ float g_Whhl[(size_t)GL * L];
__device__ float g_Wihs[(size_t)GS * S];
__device__ float g_Whhs[(size_t)GS * S];
__device__ float g_bl[GL];
__device__ float g_bs[GS];
__device__ float g_hl[2][Bb * L];
__device__ float g_cl[2][Bb * L];
__device__ float g_hs[2][Bb * S];
__device__ float g_cs[2][Bb * S];
__device__ int   g_rflag[Bb];

// C[m,n] = sum_k A[m,k]*B[n,k]  (both row-major, NT)
template <int BM, int BN, int TM, int TN>
DEV_INLINE void gemm_core(const float* __restrict__ A, int lda,
                          const float* __restrict__ Bw, int ldb,
                          int M, int N, int K, int m0, int n0,
                          float* __restrict__ As, float* __restrict__ Bs,
                          float (&acc)[TM][TN])
{
    constexpr int THREADS = (BM / TM) * (BN / TN);
    constexpr int LDAS = BM + 4, LDBS = BN + 4;
    const int tid = threadIdx.x;
    const int tx = tid % (BN / TN), ty = tid / (BN / TN);
    const int tm0 = ty * TM, tn0 = tx * TN;

    #pragma unroll
    for (int i = 0; i < TM; i++)
        #pragma unroll
        for (int j = 0; j < TN; j++) acc[i][j] = 0.f;

    for (int k0 = 0; k0 < K; k0 += BK) {
        __syncthreads();
        #pragma unroll
        for (int i = 0; i < (BM * BK / 4) / THREADS; i++) {
            int idx = tid + i * THREADS;
            int row = idx / (BK / 4), kq = idx % (BK / 4);
            float4 v = make_float4(0.f, 0.f, 0.f, 0.f);
            int gm = m0 + row;
            if (gm < M) v = *reinterpret_cast<const float4*>(A + (size_t)gm * lda + k0 + kq * 4);
            As[(kq * 4 + 0) * LDAS + row] = v.x;
            As[(kq * 4 + 1) * LDAS + row] = v.y;
            As[(kq * 4 + 2) * LDAS + row] = v.z;
            As[(kq * 4 + 3) * LDAS + row] = v.w;
        }
        #pragma unroll
        for (int i = 0; i < (BN * BK / 4) / THREADS; i++) {
            int idx = tid + i * THREADS;
            int row = idx / (BK / 4), kq = idx % (BK / 4);
            float4 v = make_float4(0.f, 0.f, 0.f, 0.f);
            int gn = n0 + row;
            if (gn < N) v = *reinterpret_cast<const float4*>(Bw + (size_t)gn * ldb + k0 + kq * 4);
            Bs[(kq * 4 + 0) * LDBS + row] = v.x;
            Bs[(kq * 4 + 1) * LDBS + row] = v.y;
            Bs[(kq * 4 + 2) * LDBS + row] = v.z;
            Bs[(kq * 4 + 3) * LDBS + row] = v.w;
        }
        __syncthreads();
        #pragma unroll
        for (int kk = 0; kk < BK; kk++) {
            float ra[TM], rb[TN];
            #pragma unroll
            for (int i = 0; i < TM; i++) ra[i] = As[kk * LDAS + tm0 + i];
            #pragma unroll
            for (int j = 0; j < TN; j++) rb[j] = Bs[kk * LDBS + tn0 + j];
            #pragma unroll
            for (int i = 0; i < TM; i++)
                #pragma unroll
                for (int j = 0; j < TN; j++)
                    acc[i][j] = fmaf(ra[i], rb[j], acc[i][j]);
        }
    }
}

// MODE 0: +bias   MODE 1: relu((v+bias)*gamma*BN_RS + beta)
template <int MODE>
__global__ void __launch_bounds__(256)
gemm_nt(const float* __restrict__ A, int lda, const float* __restrict__ Bw, int ldb,
        float* __restrict__ C, int ldc, int M, int N, int K,
        const float* __restrict__ bias, const float* __restrict__ gamma,
        const float* __restrict__ beta)
{
    constexpr int BM = 128, BN = 128, TM = 8, TN = 8;
    __shared__ float As[BK * (BM + 4)];
    __shared__ float Bs[BK * (BN + 4)];
    const int m0 = blockIdx.y * BM, n0 = blockIdx.x * BN;
    float acc[TM][TN];
    gemm_core<BM, BN, TM, TN>(A, lda, Bw, ldb, M, N, K, m0, n0, As, Bs, acc);
    const int tid = threadIdx.x;
    const int tx = tid % (BN / TN), ty = tid / (BN / TN);
    #pragma unroll
    for (int i = 0; i < TM; i++) {
        int m = m0 + ty * TM + i;
        if (m >= M) continue;
        #pragma unroll
        for (int j = 0; j < TN; j++) {
            int n = n0 + tx * TN + j;
            if (n >= N) continue;
            float v = acc[i][j] + bias[n];
            if (MODE == 1) v = fmaxf(fmaf(v, gamma[n] * BN_RS, beta[n]), 0.f);
            C[(size_t)m * ldc + n] = v;
        }
    }
}

DEV_INLINE float sigf(float x) { return 1.0f / (1.0f + expf(-x)); }

// per step: small LSTM cell (fused in GEMM epilogue) + hard-gate decision
__global__ void __launch_bounds__(256)
step_small(int t, int cur, const float* __restrict__ Wg, float* __restrict__ dout)
{
    constexpr int BM = 64, BN = 128, TM = 4, TN = 8;
    constexpr int GX = GS / BN, GY = Bb / BM;   // 16, 4
    const int nxt = cur ^ 1;
    const int bid = blockIdx.x;
    __shared__ float As[BK * (BM + 4)];
    __shared__ float Bs[BK * (BN + 4)];

    if (bid < GX * GY) {
        const int m0 = (bid / GX) * BM, n0 = (bid % GX) * BN;
        float acc[TM][TN];
        gemm_core<BM, BN, TM, TN>(g_hs[cur], S, g_Whhs, S, Bb, GS, S, m0, n0, As, Bs, acc);
        const int tid = threadIdx.x;
        const int tx = tid % (BN / TN), ty = tid / (BN / TN);
        #pragma unroll
        for (int i = 0; i < TM; i++) {
            int b = m0 + ty * TM + i;
            size_t row = (size_t)b * T + t;
            #pragma unroll
            for (int q = 0; q < TN / 4; q++) {
                int n = n0 + tx * TN + q * 4;
                int j = n >> 2;
                float4 ig = *reinterpret_cast<const float4*>(g_igs + row * GS + n);
                float c2 = sigf(acc[i][q*4+1] + ig.y) * g_cs[cur][b * S + j]
                         + sigf(acc[i][q*4+0] + ig.x) * tanhf(acc[i][q*4+2] + ig.z);
                float h2 = sigf(acc[i][q*4+3] + ig.w) * tanhf(c2);
                g_cs[nxt][b * S + j] = c2;
                g_hs[nxt][b * S + j] = h2;
            }
        }
    } else {
        const int gb = bid - GX * GY;
        const int tid = threadIdx.x;
        const int sub = tid >> 4, lane = tid & 15;
        const int b = gb * 16 + sub;
        const float* hl = g_hl[cur] + b * L;
        const float* cl = g_cl[cur] + b * L;
        const float* w0 = Wg + S;
        const float* w1 = Wg + CAT + S;
        float l0 = 0.f, l1 = 0.f;
        for (int k = lane; k < L; k += 16) {
            float hv = hl[k], cv = cl[k];
            l0 = fmaf(hv, w0[k], l0); l0 = fmaf(cv, w0[L + k], l0);
            l1 = fmaf(hv, w1[k], l1); l1 = fmaf(cv, w1[L + k], l1);
        }
        #pragma unroll
        for (int off = 8; off; off >>= 1) {
            l0 += __shfl_down_sync(0xffffffffu, l0, off, 16);
            l1 += __shfl_down_sync(0xffffffffu, l1, off, 16);
        }
        if (lane == 0) {
            int row = b * T + t;
            l0 += g_gpre[row * 2 + 0];
            l1 += g_gpre[row * 2 + 1];
            int pick1 = (l1 > l0);
            g_rflag[b] = pick1 ? 0 : 1;
            size_t o = (size_t)RS_OFF + ((size_t)t * Bb + b) * 2;
            dout[o]     = pick1 ? 0.0f : 1.0f;
            dout[o + 1] = pick1 ? 1.0f : 0.0f;
        }
    }
}

// per step: large LSTM cell + gated combine (fused epilogue)
__global__ void __launch_bounds__(256)
step_large(int t, int cur)
{
    constexpr int BM = 64, BN = 128, TM = 4, TN = 8;
    const int nxt = cur ^ 1;
    __shared__ float As[BK * (BM + 4)];
    __shared__ float Bs[BK * (BN + 4)];
    const int m0 = blockIdx.y * BM, n0 = blockIdx.x * BN;
    float acc[TM][TN];
    gemm_core<BM, BN, TM, TN>(g_hl[cur], L, g_Whhl, L, Bb, GL, L, m0, n0, As, Bs, acc);
    const int tid = threadIdx.x;
    const int tx = tid % (BN / TN), ty = tid / (BN / TN);
    #pragma unroll
    for (int i = 0; i < TM; i++) {
        int b = m0 + ty * TM + i;
        size_t row = (size_t)b * T + t;
        int r0 = g_rflag[b];
        #pragma unroll
        for (int q = 0; q < TN / 4; q++) {
            int n = n0 + tx * TN + q * 4;
            int j = n >> 2;
            float4 ig = *reinterpret_cast<const float4*>(g_igl + row * GL + n);
            float cold = g_cl[cur][b * L + j];
            float hold = g_hl[cur][b * L + j];
            float c2 = sigf(acc[i][q*4+1] + ig.y) * cold
                     + sigf(acc[i][q*4+0] + ig.x) * tanhf(acc[i][q*4+2] + ig.z);
            float h2 = sigf(acc[i][q*4+3] + ig.w) * tanhf(c2);
            float hn, cn;
            if (r0)         { hn = h2;                   cn = c2; }
            else if (j < S) { hn = g_hs[nxt][b * S + j]; cn = g_cs[nxt][b * S + j]; }
            else            { hn = hold;                 cn = cold; }
            g_hl[nxt][b * L + j] = hn;
            g_cl[nxt][b * L + j] = cn;
        }
    }
}

__global__ void permute_w(const float* __restrict__ src, float* __restrict__ dst,
                          int H, int K)
{
    size_t total = (size_t)4 * H * K;
    size_t stride = (size_t)gridDim.x * blockDim.x;
    for (size_t i = (size_t)blockIdx.x * blockDim.x + threadIdx.x; i < total; i += stride) {
        size_t k = i % K;
        int n = (int)(i / K), j = n >> 2, g = n & 3;
        dst[i] = src[(size_t)(g * H + j) * K + k];
    }
}

__global__ void permute_bias(const float* __restrict__ b1, const float* __restrict__ b2,
                             float* __restrict__ dst, int H)
{
    int n = blockIdx.x * blockDim.x + threadIdx.x;
    if (n < 4 * H) { int j = n >> 2, g = n & 3; dst[n] = b1[g * H + j] + b2[g * H + j]; }
}

__global__ void init_states()
{
    int i = blockIdx.x * blockDim.x + threadIdx.x;
    int stride = gridDim.x * blockDim.x;
    for (int k = i; k < Bb * L; k += stride) { g_hl[0][k] = 0.f; g_cl[0][k] = 0.f; }
    for (int k = i; k < Bb * S; k += stride) { g_hs[0][k] = 0.f; g_cs[0][k] = 0.f; }
}

__global__ void gpre_kernel(const float* __restrict__ Wg, const float* __restrict__ bg)
{
    int row = blockIdx.x * 8 + (threadIdx.x >> 5);
    int lane = threadIdx.x & 31;
    if (row >= BT) return;
    const float* s = g_featcat + (size_t)row * CAT + DX;
    float l0 = 0.f, l1 = 0.f;
    for (int k = lane; k < S; k += 32) {
        float v = s[k];
        l0 = fmaf(v, Wg[k], l0);
        l1 = fmaf(v, Wg[CAT + k], l1);
    }
    #pragma unroll
    for (int off = 16; off; off >>= 1) {
        l0 += __shfl_down_sync(0xffffffffu, l0, off);
        l1 += __shfl_down_sync(0xffffffffu, l1, off);
    }
    if (lane == 0) {
        g_gpre[row * 2 + 0] = l0 + bg[0];
        g_gpre[row * 2 + 1] = l1 + bg[1];
    }
}

extern "C" void kernel_launch(void* const* d_in, const int* in_sizes, int n_in,
                              void* d_out, int out_size)
{
    const float* x     = (const float*)d_in[0];
    const float* xs    = (const float*)d_in[1];
    const float* W_p   = (const float*)d_in[2];
    const float* b_p   = (const float*)d_in[3];
    const float* g_p   = (const float*)d_in[4];
    const float* be_p  = (const float*)d_in[5];
    const float* W_s   = (const float*)d_in[6];
    const float* b_s   = (const float*)d_in[7];
    const float* g_s   = (const float*)d_in[8];
    const float* be_s  = (const float*)d_in[9];
    const float* Wih_l = (const float*)d_in[10];
    const float* Whh_l = (const float*)d_in[11];
    const float* bih_l = (const float*)d_in[12];
    const float* bhh_l = (const float*)d_in[13];
    const float* Wih_s = (const float*)d_in[14];
    const float* Whh_s = (const float*)d_in[15];
    const float* bih_s = (const float*)d_in[16];
    const float* bhh_s = (const float*)d_in[17];
    const float* W_g   = (const float*)d_in[18];
    const float* b_g   = (const float*)d_in[19];
    const float* W_c   = (const float*)d_in[20];
    const float* b_c   = (const float*)d_in[21];
    float* out = (float*)d_out;
    (void)in_sizes; (void)n_in; (void)out_size;

    float *featcat, *igl, *igs, *Wihl, *Whhl, *Wihs, *Whhs, *bl, *bs, *hl0;
    cudaGetSymbolAddress((void**)&featcat, g_featcat);
    cudaGetSymbolAddress((void**)&igl,  g_igl);
    cudaGetSymbolAddress((void**)&igs,  g_igs);
    cudaGetSymbolAddress((void**)&Wihl, g_Wihl);
    cudaGetSymbolAddress((void**)&Whhl, g_Whhl);
    cudaGetSymbolAddress((void**)&Wihs, g_Wihs);
    cudaGetSymbolAddress((void**)&Whhs, g_Whhs);
    cudaGetSymbolAddress((void**)&bl,   g_bl);
    cudaGetSymbolAddress((void**)&bs,   g_bs);
    cudaGetSymbolAddress((void**)&hl0,  g_hl);

    init_states<<<256, 256>>>();
    permute_w<<<2048, 256>>>(Wih_l, Wihl, L, CAT);
    permute_w<<<2048, 256>>>(Whh_l, Whhl, L, L);
    permute_w<<<1024, 256>>>(Wih_s, Wihs, S, S);
    permute_w<<<1024, 256>>>(Whh_s, Whhs, S, S);
    permute_bias<<<(GL + 255) / 256, 256>>>(bih_l, bhh_l, bl, L);
    permute_bias<<<(GS + 255) / 256, 256>>>(bih_s, bhh_s, bs, S);

    // feats = bn_relu(x @ W_p^T + b_p) -> featcat[:, :2048]
    gemm_nt<1><<<dim3(DX / 128, BT / 128), 256>>>(x, DX, W_p, DX, featcat, CAT,
                                                  BT, DX, DX, b_p, g_p, be_p);
    // sfeats = bn_relu(xs @ W_s^T + b_s) -> featcat[:, 2048:]
    gemm_nt<1><<<dim3(S / 128, BT / 128), 256>>>(xs, DXS, W_s, DXS, featcat + DX, CAT,
                                                 BT, S, DXS, b_s, g_s, be_s);
    // input-side gate preactivations (permuted), biases folded in
    gemm_nt<0><<<dim3(GS / 128, BT / 128), 256>>>(featcat + DX, CAT, Wihs, S, igs, GS,
                                                  BT, GS, S, bs, nullptr, nullptr);
    gemm_nt<0><<<dim3(GL / 128, BT / 128), 256>>>(featcat, CAT, Wihl, CAT, igl, GL,
                                                  BT, GL, CAT, bl, nullptr, nullptr);
    gpre_kernel<<<BT / 8, 256>>>(W_g, b_g);

    for (int t = 0; t < T; t++) {
        int cur = t & 1;
        step_small<<<(GS / 128) * (Bb / 64) + Bb / 16, 256>>>(t, cur, W_g, out);
        step_large<<<dim3(GL / 128, Bb / 64), 256>>>(t, cur);
    }
    // logits = h_l @ W_c^T + b_c   (final states land in buffer 0 after 64 steps)
    gemm_nt<0><<<dim3(2, 2), 256>>>(hl0, L, W_c, L, out, NC, Bb, NC, L,
                                    b_c, nullptr, nullptr);
}